// round 2
// baseline (speedup 1.0000x reference)
#include <cuda_runtime.h>

// Problem constants
#define Bc 4
#define Nc 100
#define Cc 81
#define Mc 20
#define Lc 65536
// Tiling
#define TN 10              // n's per block (100/10 = 10 tiles, exact)
#define NTILES (Nc / TN)   // 10
#define LSEG 16            // L split factor
#define SEGLEN (Lc / LSEG) // 4096
#define CHUNK 512          // t smem chunk (floats per m-row)
#define TPB 128

// Scratch (device globals: no allocation allowed)
__device__ float g_pt[Bc * Nc * Mc]; // sum p*t
__device__ float g_sp[Bc * Nc];      // sum p
__device__ float g_st[Bc * Mc];      // sum t

__global__ void zero_kernel() {
    int i = blockIdx.x * 256 + threadIdx.x;
    if (i < Bc * Nc * Mc) g_pt[i] = 0.0f;
    if (i < Bc * Nc) g_sp[i] = 0.0f;
}

__device__ __forceinline__ float fsigmoid(float x) {
    // 1 / (1 + exp(-x)) via ex2.approx + rcp.approx (both ~1e-6 rel err)
    float e;
    asm("ex2.approx.f32 %0, %1;" : "=f"(e) : "f"(-1.44269504f * x));
    float r;
    asm("rcp.approx.f32 %0, %1;" : "=f"(r) : "f"(1.0f + e));
    return r;
}

// st[b,m] = sum_L gt_masks[b,m,:]
__global__ void st_kernel(const float* __restrict__ gt) {
    int bm = blockIdx.x; // 0..79
    const float4* row = (const float4*)(gt + (size_t)bm * Lc);
    float s = 0.0f;
    for (int i = threadIdx.x; i < Lc / 4; i += 256) {
        float4 v = row[i];
        s += (v.x + v.y) + (v.z + v.w);
    }
#pragma unroll
    for (int o = 16; o; o >>= 1) s += __shfl_down_sync(0xffffffffu, s, o);
    __shared__ float r[8];
    if ((threadIdx.x & 31) == 0) r[threadIdx.x >> 5] = s;
    __syncthreads();
    if (threadIdx.x == 0) {
        float t = 0.0f;
#pragma unroll
        for (int w = 0; w < 8; w++) t += r[w];
        g_st[bm] = t;
    }
}

// Main fused kernel: per block (n-tile of TN, batch b, L-segment)
// acc[TN][Mc] in registers; t chunk staged in smem; p streamed from gmem
// with sigmoid computed once per element.
__global__ void __launch_bounds__(TPB) main_kernel(const float* __restrict__ pm,
                                                   const float* __restrict__ gt) {
    __shared__ float t_s[Mc][CHUNK];           // 40 KB
    __shared__ float red[TPB / 32][TN * Mc + TN]; // 4 x 210

    const int b = blockIdx.y;
    const int n0 = blockIdx.x * TN;
    const int L0 = blockIdx.z * SEGLEN;
    const int tid = threadIdx.x;

    float acc[TN][Mc];
    float sp[TN];
#pragma unroll
    for (int i = 0; i < TN; i++) {
        sp[i] = 0.0f;
#pragma unroll
        for (int m = 0; m < Mc; m++) acc[i][m] = 0.0f;
    }

    const float* pmb = pm + (unsigned)(b * Nc + n0) * Lc + L0;
    const float* gtb = gt + (unsigned)(b * Mc) * Lc + L0;

    for (int c0 = 0; c0 < SEGLEN; c0 += CHUNK) {
        // stage t chunk: Mc x CHUNK floats, float4 loads
#pragma unroll 4
        for (int j = tid; j < Mc * (CHUNK / 4); j += TPB) {
            int m = j / (CHUNK / 4);
            int l4 = j - m * (CHUNK / 4);
            float4 v = *((const float4*)(gtb + (unsigned)m * Lc + c0) + l4);
            *(float4*)&t_s[m][l4 * 4] = v;
        }
        __syncthreads();

#pragma unroll
        for (int k = 0; k < CHUNK / TPB; k++) {
            int l = tid + k * TPB;
            float p[TN];
#pragma unroll
            for (int i = 0; i < TN; i++) {
                float x = __ldcs(pmb + (unsigned)i * Lc + c0 + l); // streamed, evict-first
                p[i] = fsigmoid(x);
                sp[i] += p[i];
            }
#pragma unroll
            for (int m = 0; m < Mc; m++) {
                float tv = t_s[m][l];
#pragma unroll
                for (int i = 0; i < TN; i++) acc[i][m] = fmaf(p[i], tv, acc[i][m]);
            }
        }
        __syncthreads();
    }

    // intra-warp tree reduce, then cross-warp via smem, then global atomics
    const int lane = tid & 31, w = tid >> 5;
#pragma unroll
    for (int i = 0; i < TN; i++) {
#pragma unroll
        for (int m = 0; m < Mc; m++) {
            float v = acc[i][m];
#pragma unroll
            for (int o = 16; o; o >>= 1) v += __shfl_down_sync(0xffffffffu, v, o);
            if (lane == 0) red[w][i * Mc + m] = v;
        }
    }
#pragma unroll
    for (int i = 0; i < TN; i++) {
        float v = sp[i];
#pragma unroll
        for (int o = 16; o; o >>= 1) v += __shfl_down_sync(0xffffffffu, v, o);
        if (lane == 0) red[w][TN * Mc + i] = v;
    }
    __syncthreads();
    for (int idx = tid; idx < TN * Mc + TN; idx += TPB) {
        float s = red[0][idx] + red[1][idx] + red[2][idx] + red[3][idx];
        if (idx < TN * Mc) {
            int i = idx / Mc, m = idx - i * Mc;
            atomicAdd(&g_pt[(b * Nc + n0 + i) * Mc + m], s);
        } else {
            atomicAdd(&g_sp[b * Nc + n0 + (idx - TN * Mc)], s);
        }
    }
}

// Final combine: 8000 outputs
// NOTE: gt_labels is int32 on-device (JAX x64 disabled downcasts jnp.int64
// to int32). Read as int; clamp defensively so a bad label can never trap.
__global__ void combine_kernel(const float* __restrict__ logits,
                               const int* __restrict__ labels,
                               float* __restrict__ out) {
    int idx = blockIdx.x * 256 + threadIdx.x;
    if (idx >= Bc * Nc * Mc) return;
    int m = idx % Mc;
    int n = (idx / Mc) % Nc;
    int b = idx / (Mc * Nc);

    float pt = g_pt[idx];
    float sp = g_sp[b * Nc + n];
    float st = g_st[b * Mc + m];
    int lab = labels[b * Mc + m];
    lab = lab < 0 ? 0 : (lab >= Cc ? Cc - 1 : lab);
    float logit = logits[(b * Nc + n) * Cc + lab];

    const float invL = 1.0f / (float)Lc;
    float cost_class = -logit;
    float cost_mask = -(2.0f * pt + (float)Lc - sp - st) * invL;
    float cost_dice = 1.0f - (2.0f * pt + 1.0f) / (sp + st + 1.0f);
    out[idx] = cost_class + cost_mask + cost_dice;
}

extern "C" void kernel_launch(void* const* d_in, const int* in_sizes, int n_in,
                              void* d_out, int out_size) {
    const float* pred_logits = (const float*)d_in[0]; // (4,100,81) f32
    const float* pred_masks = (const float*)d_in[1];  // (4,100,256,256) f32
    const int* gt_labels = (const int*)d_in[2];       // (4,20) int32 (x64 disabled)
    const float* gt_masks = (const float*)d_in[3];    // (4,20,256,256) f32
    float* out = (float*)d_out;                       // (4,100,20) f32

    zero_kernel<<<(Bc * Nc * Mc + 255) / 256, 256>>>();
    st_kernel<<<Bc * Mc, 256>>>(gt_masks);
    dim3 grid(NTILES, Bc, LSEG);
    main_kernel<<<grid, TPB>>>(pred_masks, gt_masks);
    combine_kernel<<<(Bc * Nc * Mc + 255) / 256, 256>>>(pred_logits, gt_labels, out);
}

// round 3
// speedup vs baseline: 1.4020x; 1.4020x over previous
#include <cuda_runtime.h>

// Problem constants
#define Bc 4
#define Nc 100
#define Cc 81
#define Mc 20
#define Lc 65536
// Tiling
#define TN 10               // n's per block (100/10 = 10 tiles, exact)
#define NTILES (Nc / TN)    // 10
#define LSEG 32             // L split factor
#define SEGLEN (Lc / LSEG)  // 2048
#define CHUNK 256           // l's staged per iteration
#define TPB 128
#define MW 5                // m's per warp (4 warps x 5 = 20)

// Scratch (device globals: no runtime allocation allowed)
__device__ float g_pt[Bc * Nc * Mc]; // sum p*t
__device__ float g_sp[Bc * Nc];      // sum p
__device__ float g_st[Bc * Mc];      // sum t

__device__ __forceinline__ float fsigmoid(float x) {
    float e;
    asm("ex2.approx.f32 %0, %1;" : "=f"(e) : "f"(-1.44269504f * x));
    float r;
    asm("rcp.approx.f32 %0, %1;" : "=f"(r) : "f"(1.0f + e));
    return r;
}

// Packed fp32x2 FMA (Blackwell): d = a*b + d, lanewise on two packed floats.
__device__ __forceinline__ void fma2(unsigned long long& d, unsigned long long a,
                                     unsigned long long b) {
    asm("fma.rn.f32x2 %0, %1, %2, %0;" : "+l"(d) : "l"(a), "l"(b));
}

// Fused init: blocks 0..79 compute st[b,m]; block 80 zeros g_pt/g_sp.
__global__ void init_kernel(const float* __restrict__ gt) {
    if (blockIdx.x < Bc * Mc) {
        int bm = blockIdx.x;
        const float4* row = (const float4*)(gt + (size_t)bm * Lc);
        float s = 0.0f;
        for (int i = threadIdx.x; i < Lc / 4; i += 256) {
            float4 v = row[i];
            s += (v.x + v.y) + (v.z + v.w);
        }
#pragma unroll
        for (int o = 16; o; o >>= 1) s += __shfl_down_sync(0xffffffffu, s, o);
        __shared__ float r[8];
        if ((threadIdx.x & 31) == 0) r[threadIdx.x >> 5] = s;
        __syncthreads();
        if (threadIdx.x == 0) {
            float t = 0.0f;
#pragma unroll
            for (int w = 0; w < 8; w++) t += r[w];
            g_st[bm] = t;
        }
    } else {
        for (int i = threadIdx.x; i < Bc * Nc * Mc; i += 256) g_pt[i] = 0.0f;
        for (int i = threadIdx.x; i < Bc * Nc; i += 256) g_sp[i] = 0.0f;
    }
}

// Main fused kernel.
// Block = (n-tile of 10, batch b, L-segment). 4 warps; warp w owns m in
// [w*5, w*5+5). Stage p (with sigmoid applied) and t chunks in smem; inner
// loop uses packed f32x2 FMAs, each lane covering two adjacent l's.
__global__ void __launch_bounds__(TPB) main_kernel(const float* __restrict__ pm,
                                                   const float* __restrict__ gt) {
    __shared__ float p_s[TN][CHUNK]; // 10 KB
    __shared__ float t_s[Mc][CHUNK]; // 20 KB

    const int b = blockIdx.y;
    const int n0 = blockIdx.x * TN;
    const int L0 = blockIdx.z * SEGLEN;
    const int tid = threadIdx.x;
    const int wid = tid >> 5, lane = tid & 31;
    const int m0 = wid * MW;

    unsigned long long acc2[TN][MW]; // packed float2 accumulators
#pragma unroll
    for (int i = 0; i < TN; i++)
#pragma unroll
        for (int m = 0; m < MW; m++) acc2[i][m] = 0ull;
    float sp_loc[5] = {0.f, 0.f, 0.f, 0.f, 0.f}; // rows (tid>=64)+2k

    const float* pmb = pm + (unsigned)(b * Nc + n0) * Lc + L0;
    const float* gtb = gt + (unsigned)(b * Mc) * Lc + L0;

    for (int c0 = 0; c0 < SEGLEN; c0 += CHUNK) {
        // Stage p chunk (apply sigmoid once); accumulate per-row sp partials.
        // Linear j over [TN][CHUNK/4] float4s: j = tid + k*128, row = j>>6.
#pragma unroll
        for (int k = 0; k < TN * (CHUNK / 4) / TPB; k++) { // 5
            int j = tid + k * TPB;
            int i = j >> 6, e4 = j & 63;
            float4 v = __ldcs((const float4*)(pmb + (unsigned)i * Lc + c0) + e4);
            v.x = fsigmoid(v.x);
            v.y = fsigmoid(v.y);
            v.z = fsigmoid(v.z);
            v.w = fsigmoid(v.w);
            sp_loc[k] += (v.x + v.y) + (v.z + v.w);
            *(float4*)&p_s[i][e4 * 4] = v;
        }
        // Stage t chunk.
#pragma unroll
        for (int k = 0; k < Mc * (CHUNK / 4) / TPB; k++) { // 10
            int j = tid + k * TPB;
            int m = j >> 6, e4 = j & 63;
            *(float4*)&t_s[m][e4 * 4] =
                *((const float4*)(gtb + (unsigned)m * Lc + c0) + e4);
        }
        __syncthreads();

#pragma unroll
        for (int it = 0; it < CHUNK / 64; it++) { // 4 iters of 64 l's
            const int l = it * 64 + lane * 2;
            unsigned long long t2[MW];
#pragma unroll
            for (int m = 0; m < MW; m++)
                t2[m] = *(const unsigned long long*)&t_s[m0 + m][l];
#pragma unroll
            for (int i = 0; i < TN; i++) {
                unsigned long long p2 = *(const unsigned long long*)&p_s[i][l];
#pragma unroll
                for (int m = 0; m < MW; m++) fma2(acc2[i][m], p2, t2[m]);
            }
        }
        __syncthreads();
    }

    // Reduce acc2 within warp -> atomicAdd to g_pt (warps own disjoint m's).
#pragma unroll
    for (int i = 0; i < TN; i++) {
#pragma unroll
        for (int m = 0; m < MW; m++) {
            float2 f = *(float2*)&acc2[i][m];
            float v = f.x + f.y;
#pragma unroll
            for (int o = 16; o; o >>= 1) v += __shfl_down_sync(0xffffffffu, v, o);
            if (lane == 0)
                atomicAdd(&g_pt[(b * Nc + n0 + i) * Mc + m0 + m], v);
        }
    }
    // Reduce sp partials: all lanes of a warp share the same row parity.
    const int par = tid >> 6; // 0 for warps 0,1; 1 for warps 2,3
#pragma unroll
    for (int k = 0; k < 5; k++) {
        float v = sp_loc[k];
#pragma unroll
        for (int o = 16; o; o >>= 1) v += __shfl_down_sync(0xffffffffu, v, o);
        if (lane == 0) atomicAdd(&g_sp[b * Nc + n0 + par + 2 * k], v);
    }
}

// Final combine: 8000 outputs.
// gt_labels is int32 on-device (JAX x64 disabled downcasts int64). Clamp
// defensively so a bad label can never trap.
__global__ void combine_kernel(const float* __restrict__ logits,
                               const int* __restrict__ labels,
                               float* __restrict__ out) {
    int idx = blockIdx.x * 256 + threadIdx.x;
    if (idx >= Bc * Nc * Mc) return;
    int m = idx % Mc;
    int n = (idx / Mc) % Nc;
    int b = idx / (Mc * Nc);

    float pt = g_pt[idx];
    float sp = g_sp[b * Nc + n];
    float st = g_st[b * Mc + m];
    int lab = labels[b * Mc + m];
    lab = lab < 0 ? 0 : (lab >= Cc ? Cc - 1 : lab);
    float logit = logits[(b * Nc + n) * Cc + lab];

    const float invL = 1.0f / (float)Lc;
    float cost_class = -logit;
    float cost_mask = -(2.0f * pt + (float)Lc - sp - st) * invL;
    float cost_dice = 1.0f - (2.0f * pt + 1.0f) / (sp + st + 1.0f);
    out[idx] = cost_class + cost_mask + cost_dice;
}

extern "C" void kernel_launch(void* const* d_in, const int* in_sizes, int n_in,
                              void* d_out, int out_size) {
    const float* pred_logits = (const float*)d_in[0]; // (4,100,81) f32
    const float* pred_masks = (const float*)d_in[1];  // (4,100,256,256) f32
    const int* gt_labels = (const int*)d_in[2];       // (4,20) int32
    const float* gt_masks = (const float*)d_in[3];    // (4,20,256,256) f32
    float* out = (float*)d_out;                       // (4,100,20) f32

    init_kernel<<<Bc * Mc + 1, 256>>>(gt_masks);
    dim3 grid(NTILES, Bc, LSEG);
    main_kernel<<<grid, TPB>>>(pred_masks, gt_masks);
    combine_kernel<<<(Bc * Nc * Mc + 255) / 256, 256>>>(pred_logits, gt_labels, out);
}

// round 4
// speedup vs baseline: 1.6344x; 1.1658x over previous
#include <cuda_runtime.h>

// Problem constants
#define Bc 4
#define Nc 100
#define Cc 81
#define Mc 20
#define Lc 65536
// Tiling
#define TN 10               // n's per block
#define NTILES (Nc / TN)    // 10
#define LSEG 32             // L split factor
#define SEGLEN (Lc / LSEG)  // 2048
#define CHUNK 256           // l's per staged chunk
#define NCHUNK (SEGLEN / CHUNK) // 8
#define TPB 128
#define MW 5                // m's per warp

// Partial-sum scratch (written unconditionally -> no zeroing needed)
__device__ float g_pt_part[LSEG * Bc * Nc * Mc]; // 1.02 MB
__device__ float g_sp_part[LSEG * Bc * Nc];
__device__ float g_st_part[LSEG * Bc * Mc];

__device__ __forceinline__ float fsigmoid(float x) {
    float e;
    asm("ex2.approx.f32 %0, %1;" : "=f"(e) : "f"(-1.44269504f * x));
    float r;
    asm("rcp.approx.f32 %0, %1;" : "=f"(r) : "f"(1.0f + e));
    return r;
}
__device__ __forceinline__ void fma2(unsigned long long& d, unsigned long long a,
                                     unsigned long long b) {
    asm("fma.rn.f32x2 %0, %1, %2, %0;" : "+l"(d) : "l"(a), "l"(b));
}
__device__ __forceinline__ void add2(unsigned long long& d, unsigned long long a) {
    asm("add.rn.f32x2 %0, %0, %1;" : "+l"(d) : "l"(a));
}
__device__ __forceinline__ unsigned smem_u32(const void* p) {
    unsigned a;
    asm("{ .reg .u64 t; cvta.to.shared.u64 t, %1; cvt.u32.u64 %0, t; }"
        : "=r"(a) : "l"(p));
    return a;
}
__device__ __forceinline__ void cp16(unsigned dst, const void* src) {
    asm volatile("cp.async.ca.shared.global [%0], [%1], 16;"
                 :: "r"(dst), "l"(src) : "memory");
}

// Main kernel. Block = (n-tile, b, L-segment). 4 warps; warp w owns m-rows
// [5w, 5w+5). t staged via cp.async double-buffered; p staged with sigmoid
// applied (LDG->MUFU->STS). Inner loop: LDS.128 + packed f32x2 FMAs,
// 4 l's per lane. Partials written to private slots (no atomics).
__global__ void __launch_bounds__(TPB) main_kernel(const float* __restrict__ pm,
                                                   const float* __restrict__ gt) {
    __shared__ float t_s[2][Mc][CHUNK]; // 40 KB
    __shared__ float p_s[2][TN][CHUNK]; // 20 KB
    __shared__ float red_sp[4][MW];

    const int b = blockIdx.y;
    const int n0 = blockIdx.x * TN;
    const int z = blockIdx.z;
    const int L0 = z * SEGLEN;
    const int tid = threadIdx.x;
    const int wid = tid >> 5, lane = tid & 31;
    const int m0 = wid * MW;
    const bool do_st = (blockIdx.x == 0);

    unsigned long long acc2[TN][MW];
#pragma unroll
    for (int i = 0; i < TN; i++)
#pragma unroll
        for (int m = 0; m < MW; m++) acc2[i][m] = 0ull;
    unsigned long long st2[MW] = {0ull, 0ull, 0ull, 0ull, 0ull};
    float sp_loc[MW] = {0.f, 0.f, 0.f, 0.f, 0.f};

    const float* pmb = pm + (unsigned)(b * Nc + n0) * Lc + L0;
    const float* gtb = gt + (unsigned)(b * Mc) * Lc + L0;

    // Prefetch t chunk 0 into buf 0
    {
        const unsigned tbase = smem_u32(&t_s[0][0][0]);
#pragma unroll
        for (int k = 0; k < 10; k++) {
            int j = tid + k * TPB;
            int m = j >> 6, e4 = j & 63;
            cp16(tbase + (unsigned)(m * CHUNK + e4 * 4) * 4,
                 gtb + (unsigned)m * Lc + e4 * 4);
        }
        asm volatile("cp.async.commit_group;" ::: "memory");
    }

    for (int c = 0; c < NCHUNK; c++) {
        const int buf = c & 1;
        const int c0 = c * CHUNK;
        // Prefetch t chunk c+1 into other buffer
        if (c + 1 < NCHUNK) {
            const unsigned tbase = smem_u32(&t_s[buf ^ 1][0][0]);
#pragma unroll
            for (int k = 0; k < 10; k++) {
                int j = tid + k * TPB;
                int m = j >> 6, e4 = j & 63;
                cp16(tbase + (unsigned)(m * CHUNK + e4 * 4) * 4,
                     gtb + (unsigned)m * Lc + c0 + CHUNK + e4 * 4);
            }
            asm volatile("cp.async.commit_group;" ::: "memory");
        }
        // Stage p chunk c (sigmoid applied); accumulate sp partials.
#pragma unroll
        for (int k = 0; k < MW; k++) { // 5 float4s/thread
            int j = tid + k * TPB;
            int i = j >> 6, e4 = j & 63;
            float4 v = __ldcs((const float4*)(pmb + (unsigned)i * Lc + c0) + e4);
            v.x = fsigmoid(v.x);
            v.y = fsigmoid(v.y);
            v.z = fsigmoid(v.z);
            v.w = fsigmoid(v.w);
            sp_loc[k] += (v.x + v.y) + (v.z + v.w);
            *(float4*)&p_s[buf][i][e4 * 4] = v;
        }
        if (c + 1 < NCHUNK)
            asm volatile("cp.async.wait_group 1;" ::: "memory");
        else
            asm volatile("cp.async.wait_group 0;" ::: "memory");
        __syncthreads();

        // Inner compute on buf
#pragma unroll
        for (int it = 0; it < CHUNK / 128; it++) { // 2
            const int l0 = it * 128 + lane * 4;
            unsigned long long ta[MW], tb[MW];
#pragma unroll
            for (int m = 0; m < MW; m++) {
                ulonglong2 t4 = *(const ulonglong2*)&t_s[buf][m0 + m][l0];
                ta[m] = t4.x;
                tb[m] = t4.y;
            }
            if (do_st) {
#pragma unroll
                for (int m = 0; m < MW; m++) {
                    add2(st2[m], ta[m]);
                    add2(st2[m], tb[m]);
                }
            }
#pragma unroll
            for (int i = 0; i < TN; i++) {
                ulonglong2 p4 = *(const ulonglong2*)&p_s[buf][i][l0];
#pragma unroll
                for (int m = 0; m < MW; m++) {
                    fma2(acc2[i][m], p4.x, ta[m]);
                    fma2(acc2[i][m], p4.y, tb[m]);
                }
            }
        }
        __syncthreads();
    }

    // ---- Epilogue: reduce + store partials (no atomics) ----
    // pt: warps own disjoint m's.
#pragma unroll
    for (int i = 0; i < TN; i++) {
#pragma unroll
        for (int m = 0; m < MW; m++) {
            float2 f = *(float2*)&acc2[i][m];
            float v = f.x + f.y;
#pragma unroll
            for (int o = 16; o; o >>= 1) v += __shfl_down_sync(0xffffffffu, v, o);
            if (lane == 0)
                g_pt_part[((z * Bc + b) * Nc + n0 + i) * Mc + m0 + m] = v;
        }
    }
    // st: only n-tile 0 blocks; warps own disjoint m's.
    if (do_st) {
#pragma unroll
        for (int m = 0; m < MW; m++) {
            float2 f = *(float2*)&st2[m];
            float v = f.x + f.y;
#pragma unroll
            for (int o = 16; o; o >>= 1) v += __shfl_down_sync(0xffffffffu, v, o);
            if (lane == 0) g_st_part[(z * Bc + b) * Mc + m0 + m] = v;
        }
    }
    // sp: warp w covered rows (w>=2 ? 1 : 0) + 2k; pairs of warps share rows.
#pragma unroll
    for (int k = 0; k < MW; k++) {
        float v = sp_loc[k];
#pragma unroll
        for (int o = 16; o; o >>= 1) v += __shfl_down_sync(0xffffffffu, v, o);
        if (lane == 0) red_sp[wid][k] = v;
    }
    __syncthreads();
    if (tid < 2 * MW) { // 10 rows
        int par = tid / MW, k = tid % MW;
        float v = red_sp[par * 2][k] + red_sp[par * 2 + 1][k];
        g_sp_part[(z * Bc + b) * Nc + n0 + par + 2 * k] = v;
    }
}

// Combine: reduce partials over z, gather labels, emit cost matrix.
// gt_labels is int32 on-device (JAX x64-disabled downcasts int64); clamp so a
// bad label can never trap.
__global__ void combine_kernel(const float* __restrict__ logits,
                               const int* __restrict__ labels,
                               float* __restrict__ out) {
    __shared__ float s_sp[Bc * Nc]; // 400
    __shared__ float s_st[Bc * Mc]; // 80
    const int tid = threadIdx.x;

    for (int idx = tid; idx < Bc * Nc + Bc * Mc; idx += 256) {
        float s = 0.0f;
        if (idx < Bc * Nc) {
#pragma unroll 4
            for (int zz = 0; zz < LSEG; zz++) s += g_sp_part[zz * Bc * Nc + idx];
            s_sp[idx] = s;
        } else {
            int j = idx - Bc * Nc;
#pragma unroll 4
            for (int zz = 0; zz < LSEG; zz++) s += g_st_part[zz * Bc * Mc + j];
            s_st[j] = s;
        }
    }
    __syncthreads();

    const int PER = (Bc * Nc * Mc + 31) / 32; // 250 outputs per block
    for (int o = blockIdx.x * PER + tid; o < min(blockIdx.x * PER + PER, Bc * Nc * Mc);
         o += 256) {
        int m = o % Mc;
        int n = (o / Mc) % Nc;
        int b = o / (Mc * Nc);
        float pt = 0.0f;
#pragma unroll 4
        for (int zz = 0; zz < LSEG; zz++) pt += g_pt_part[zz * Bc * Nc * Mc + o];
        float sp = s_sp[b * Nc + n];
        float st = s_st[b * Mc + m];
        int lab = labels[b * Mc + m];
        lab = lab < 0 ? 0 : (lab >= Cc ? Cc - 1 : lab);
        float logit = logits[(b * Nc + n) * Cc + lab];

        const float invL = 1.0f / (float)Lc;
        float cost_class = -logit;
        float cost_mask = -(2.0f * pt + (float)Lc - sp - st) * invL;
        float cost_dice = 1.0f - (2.0f * pt + 1.0f) / (sp + st + 1.0f);
        out[o] = cost_class + cost_mask + cost_dice;
    }
}

extern "C" void kernel_launch(void* const* d_in, const int* in_sizes, int n_in,
                              void* d_out, int out_size) {
    const float* pred_logits = (const float*)d_in[0]; // (4,100,81) f32
    const float* pred_masks = (const float*)d_in[1];  // (4,100,256,256) f32
    const int* gt_labels = (const int*)d_in[2];       // (4,20) int32
    const float* gt_masks = (const float*)d_in[3];    // (4,20,256,256) f32
    float* out = (float*)d_out;                       // (4,100,20) f32

    dim3 grid(NTILES, Bc, LSEG);
    main_kernel<<<grid, TPB>>>(pred_masks, gt_masks);
    combine_kernel<<<32, 256>>>(pred_logits, gt_labels, out);
}

// round 7
// speedup vs baseline: 2.2263x; 1.3621x over previous
#include <cuda_runtime.h>
#include <cstdint>

// Problem constants
#define Bc 4
#define Nc 100
#define Cc 81
#define Mc 20
#define Lc 65536
#define LSEG 32
#define SEGLEN (Lc / LSEG)    // 2048
#define KCH 64                // K per chunk (bf16 SW128 row = 128B)
#define NCHUNK (SEGLEN / KCH) // 32
#define TPB 256

// Dynamic smem layout (bytes)
#define OFF_PBF 0             // p bf16 tiles: 2 x 16384 (128 rows x 128B)
#define OFF_TBF 32768         // t bf16 tiles: 2 x 4096  (32 rows x 128B)
#define OFF_PRAW 40960        // p raw fp32: 2 x 25600 (100 rows x 256B)
#define OFF_TRAW 92160        // t raw fp32: 2 x 5120  (20 rows x 256B)
#define SMEM_TOTAL 102400

// Partial-sum scratch
__device__ float g_pt_part[LSEG * Bc * Nc * Mc];
__device__ float g_sp_part[LSEG * Bc * Nc];
__device__ float g_st_part[LSEG * Bc * Mc];
__device__ float g_sp_f[Bc * Nc];
__device__ float g_st_f[Bc * Mc];

__device__ __forceinline__ float fsigmoid(float x) {
    float e;
    asm("ex2.approx.f32 %0, %1;" : "=f"(e) : "f"(-1.44269504f * x));
    float r;
    asm("rcp.approx.f32 %0, %1;" : "=f"(r) : "f"(1.0f + e));
    return r;
}
__device__ __forceinline__ uint32_t smem_u32(const void* p) {
    uint32_t a;
    asm("{ .reg .u64 t; cvta.to.shared.u64 t, %1; cvt.u32.u64 %0, t; }"
        : "=r"(a) : "l"(p));
    return a;
}
__device__ __forceinline__ void cp16(uint32_t dst, const void* src) {
    asm volatile("cp.async.ca.shared.global [%0], [%1], 16;"
                 :: "r"(dst), "l"(src) : "memory");
}
__device__ __forceinline__ uint32_t sw128(uint32_t off) {
    return off ^ ((off >> 3) & 0x70);
}
__device__ __forceinline__ void ldmx4(uint32_t addr, uint32_t& r0, uint32_t& r1,
                                      uint32_t& r2, uint32_t& r3) {
    asm volatile("ldmatrix.sync.aligned.m8n8.x4.shared.b16 {%0,%1,%2,%3}, [%4];"
                 : "=r"(r0), "=r"(r1), "=r"(r2), "=r"(r3) : "r"(addr));
}
__device__ __forceinline__ void ldmx2(uint32_t addr, uint32_t& r0, uint32_t& r1) {
    asm volatile("ldmatrix.sync.aligned.m8n8.x2.shared.b16 {%0,%1}, [%2];"
                 : "=r"(r0), "=r"(r1) : "r"(addr));
}
__device__ __forceinline__ void mma16816(float* c, const uint32_t* a, uint32_t b0,
                                         uint32_t b1) {
    asm volatile(
        "mma.sync.aligned.m16n8k16.row.col.f32.bf16.bf16.f32 "
        "{%0,%1,%2,%3}, {%4,%5,%6,%7}, {%8,%9}, {%0,%1,%2,%3};"
        : "+f"(c[0]), "+f"(c[1]), "+f"(c[2]), "+f"(c[3])
        : "r"(a[0]), "r"(a[1]), "r"(a[2]), "r"(a[3]), "r"(b0), "r"(b1));
}

__global__ void __launch_bounds__(TPB, 1) main_kernel(const float* __restrict__ pm,
                                                      const float* __restrict__ gt) {
    extern __shared__ char smem[];
    const uint32_t sb = smem_u32(smem);
    const int tid = threadIdx.x, wid = tid >> 5, lane = tid & 31;
    const int z = blockIdx.x, b = blockIdx.y;
    const float* pmb = pm + (size_t)(b * Nc) * Lc + z * SEGLEN;
    const float* gtb = gt + (size_t)(b * Mc) * Lc + z * SEGLEN;

    // Zero t bf16 pad region once (rows 20-31 both buffers; determinism)
    {
        uint4 zz = {0, 0, 0, 0};
        for (int i = tid; i < 8192 / 16; i += TPB)
            *(uint4*)(smem + OFF_TBF + i * 16) = zz;
    }

    // Per-lane ldmatrix address components. Swizzle decomposition:
    //   sw128(row*128 + kb) = row*128 + (kb ^ ((row&7)<<4))   for kb in [0,128)
    // (XOR source bits 7-9 come only from row*128; kb in bits 4-6 -> closed,
    //  no carries. The R6 bug was adding ks*32 AFTER swizzling -> carry to bit7.)
    const int lr = lane & 7;
    // A (x4): lanes 0-7 m0-7/k0 | 8-15 m8-15/k0 | 16-23 m0-7/k1 | 24-31 m8-15/k1
    const int a_row = 16 * wid + ((lane >> 3) & 1) * 8 + lr;
    const uint32_t a_base = (uint32_t)a_row * 128;
    const uint32_t a_x = (uint32_t)(a_row & 7) << 4;
    const uint32_t a_kb = ((lane >> 4) & 1) * 16;
    // B tiles 0/1 (x4): lanes 0-7 n0-7/k0 | 8-15 n0-7/k1 | 16-23 n8-15/k0 | 24-31 n8-15/k1
    const int b01_row = ((lane >> 4) & 1) * 8 + lr;
    const uint32_t b01_base = (uint32_t)b01_row * 128;
    const uint32_t b01_x = (uint32_t)(b01_row & 7) << 4;
    const uint32_t b01_kb = ((lane >> 3) & 1) * 16;
    // B tile 2 (x2): lanes 0-7 n16-23/k0 | 8-15 n16-23/k1
    const int b2_row = 16 + lr;
    const uint32_t b2_base = (uint32_t)b2_row * 128;
    const uint32_t b2_x = (uint32_t)(b2_row & 7) << 4;
    const uint32_t b2_kb = ((lane >> 3) & 1) * 16;

    float acc[3][4];
#pragma unroll
    for (int j = 0; j < 3; j++)
#pragma unroll
        for (int q = 0; q < 4; q++) acc[j][q] = 0.f;
    float sp_loc[7] = {0, 0, 0, 0, 0, 0, 0};
    float st0 = 0.f, st1 = 0.f;

    // Prologue: prefetch chunk 0 into buf 0
    {
#pragma unroll
        for (int k = 0; k < 7; k++) {
            int j = tid + k * TPB;
            if (j < 1600) {
                int row = j >> 4, cc = j & 15;
                cp16(sb + OFF_PRAW + row * 256 + cc * 16, pmb + (size_t)row * Lc + cc * 4);
            }
        }
        {
            int row = tid >> 4, cc = tid & 15;
            cp16(sb + OFF_TRAW + row * 256 + cc * 16, gtb + (size_t)row * Lc + cc * 4);
            if (tid < 64) {
                int r2 = 16 + row;
                cp16(sb + OFF_TRAW + r2 * 256 + cc * 16, gtb + (size_t)r2 * Lc + cc * 4);
            }
        }
        asm volatile("cp.async.commit_group;" ::: "memory");
    }

    for (int c = 0; c < NCHUNK; c++) {
        const int buf = c & 1;
        // Prefetch chunk c+1 into buf^1
        if (c + 1 < NCHUNK) {
            const int c1 = (c + 1) * KCH;
            const uint32_t pr = sb + OFF_PRAW + (buf ^ 1) * 25600;
            const uint32_t tr = sb + OFF_TRAW + (buf ^ 1) * 5120;
#pragma unroll
            for (int k = 0; k < 7; k++) {
                int j = tid + k * TPB;
                if (j < 1600) {
                    int row = j >> 4, cc = j & 15;
                    cp16(pr + row * 256 + cc * 16, pmb + (size_t)row * Lc + c1 + cc * 4);
                }
            }
            {
                int row = tid >> 4, cc = tid & 15;
                cp16(tr + row * 256 + cc * 16, gtb + (size_t)row * Lc + c1 + cc * 4);
                if (tid < 64) {
                    int r2 = 16 + row;
                    cp16(tr + r2 * 256 + cc * 16, gtb + (size_t)r2 * Lc + c1 + cc * 4);
                }
            }
            asm volatile("cp.async.commit_group;" ::: "memory");
            asm volatile("cp.async.wait_group 1;" ::: "memory");
        } else {
            asm volatile("cp.async.wait_group 0;" ::: "memory");
        }
        __syncthreads(); // raw[buf] ready; all warps done with bf16[buf] (chunk c-2)

        // Convert p: raw fp32 -> sigmoid -> bf16x2 swizzled
        const char* praw = smem + OFF_PRAW + buf * 25600;
        char* pbf = smem + OFF_PBF + buf * 16384;
#pragma unroll
        for (int k = 0; k < 7; k++) {
            int j = tid + k * TPB;
            if (j < 1600) {
                int row = j >> 4, cc = j & 15;
                float4 v = *(const float4*)(praw + row * 256 + cc * 16);
                float s0 = fsigmoid(v.x), s1 = fsigmoid(v.y);
                float s2 = fsigmoid(v.z), s3 = fsigmoid(v.w);
                sp_loc[k] += (s0 + s1) + (s2 + s3);
                uint32_t lo, hi;
                asm("cvt.rn.satfinite.bf16x2.f32 %0, %1, %2;" : "=r"(lo) : "f"(s1), "f"(s0));
                asm("cvt.rn.satfinite.bf16x2.f32 %0, %1, %2;" : "=r"(hi) : "f"(s3), "f"(s2));
                uint2 w = {lo, hi};
                *(uint2*)(pbf + sw128((uint32_t)(row * 128 + cc * 8))) = w;
            }
        }
        // Convert t (rows 0..19)
        {
            const char* traw = smem + OFF_TRAW + buf * 5120;
            char* tbf = smem + OFF_TBF + buf * 4096;
            int row = tid >> 4, cc = tid & 15;
            float4 v = *(const float4*)(traw + row * 256 + cc * 16);
            st0 += (v.x + v.y) + (v.z + v.w);
            uint32_t lo, hi;
            asm("cvt.rn.satfinite.bf16x2.f32 %0, %1, %2;" : "=r"(lo) : "f"(v.y), "f"(v.x));
            asm("cvt.rn.satfinite.bf16x2.f32 %0, %1, %2;" : "=r"(hi) : "f"(v.w), "f"(v.z));
            uint2 w = {lo, hi};
            *(uint2*)(tbf + sw128((uint32_t)(row * 128 + cc * 8))) = w;
            if (tid < 64) {
                int r2 = 16 + row;
                float4 u = *(const float4*)(traw + r2 * 256 + cc * 16);
                st1 += (u.x + u.y) + (u.z + u.w);
                asm("cvt.rn.satfinite.bf16x2.f32 %0, %1, %2;" : "=r"(lo) : "f"(u.y), "f"(u.x));
                asm("cvt.rn.satfinite.bf16x2.f32 %0, %1, %2;" : "=r"(hi) : "f"(u.w), "f"(u.z));
                uint2 w2 = {lo, hi};
                *(uint2*)(tbf + sw128((uint32_t)(r2 * 128 + cc * 8))) = w2;
            }
        }
        __syncthreads(); // bf16[buf] ready

        // Warp-level GEMM on bf16[buf]: 4 k16-steps
        const uint32_t pb = sb + OFF_PBF + buf * 16384;
        const uint32_t tb = sb + OFF_TBF + buf * 4096;
#pragma unroll
        for (int ks = 0; ks < 4; ks++) {
            const uint32_t kb = (uint32_t)ks * 32;
            uint32_t a[4], b0[2], b1[2], b2r[2];
            ldmx4(pb + a_base + ((a_kb + kb) ^ a_x), a[0], a[1], a[2], a[3]);
            ldmx4(tb + b01_base + ((b01_kb + kb) ^ b01_x), b0[0], b0[1], b1[0], b1[1]);
            ldmx2(tb + b2_base + ((b2_kb + kb) ^ b2_x), b2r[0], b2r[1]);
            mma16816(acc[0], a, b0[0], b0[1]);
            mma16816(acc[1], a, b1[0], b1[1]);
            mma16816(acc[2], a, b2r[0], b2r[1]);
        }
    }

    // ---- Epilogue: write pt partials (rows<100, cols<20) ----
    {
        const int gr = lane >> 2, qc = lane & 3;
        const int r0 = 16 * wid + gr, r1 = r0 + 8;
#pragma unroll
        for (int j = 0; j < 3; j++) {
            int col = 8 * j + 2 * qc;
            if (col + 1 < Mc) {
                if (r0 < Nc) {
                    float2 v = {acc[j][0], acc[j][1]};
                    *(float2*)&g_pt_part[((z * Bc + b) * Nc + r0) * Mc + col] = v;
                }
                if (r1 < Nc) {
                    float2 v = {acc[j][2], acc[j][3]};
                    *(float2*)&g_pt_part[((z * Bc + b) * Nc + r1) * Mc + col] = v;
                }
            }
        }
    }
    // sp partials: 16-lane groups share a p-row
#pragma unroll
    for (int k = 0; k < 7; k++) {
        float v = sp_loc[k];
#pragma unroll
        for (int o = 8; o; o >>= 1) v += __shfl_down_sync(0xffffffffu, v, o, 16);
        int row = (tid + k * TPB) >> 4;
        if ((lane & 15) == 0 && row < Nc)
            g_sp_part[(z * Bc + b) * Nc + row] = v;
    }
    // st partials
    {
        float v = st0;
#pragma unroll
        for (int o = 8; o; o >>= 1) v += __shfl_down_sync(0xffffffffu, v, o, 16);
        if ((lane & 15) == 0) g_st_part[(z * Bc + b) * Mc + (tid >> 4)] = v;
        float u = st1;
#pragma unroll
        for (int o = 8; o; o >>= 1) u += __shfl_down_sync(0xffffffffu, u, o, 16);
        if ((lane & 15) == 0 && tid < 64)
            g_st_part[(z * Bc + b) * Mc + 16 + (tid >> 4)] = u;
    }
}

// Reduce sp/st partials over z (1 block)
__global__ void reduce_kernel() {
    int i = threadIdx.x;
    if (i < Bc * Nc) {
        float s = 0.f;
#pragma unroll
        for (int zz = 0; zz < LSEG; zz++) s += g_sp_part[zz * Bc * Nc + i];
        g_sp_f[i] = s;
    } else if (i < Bc * Nc + Bc * Mc) {
        int j = i - Bc * Nc;
        float s = 0.f;
#pragma unroll
        for (int zz = 0; zz < LSEG; zz++) s += g_st_part[zz * Bc * Mc + j];
        g_st_f[j] = s;
    }
}

// Combine: thread per output, sums 32 pt partials.
// gt_labels is int32 (JAX x64-disabled); clamp so bad labels can't trap.
__global__ void combine_kernel(const float* __restrict__ logits,
                               const int* __restrict__ labels,
                               float* __restrict__ out) {
    int o = blockIdx.x * 256 + threadIdx.x;
    if (o >= Bc * Nc * Mc) return;
    int m = o % Mc;
    int n = (o / Mc) % Nc;
    int b = o / (Mc * Nc);
    float pt = 0.f;
#pragma unroll
    for (int zz = 0; zz < LSEG; zz++) pt += g_pt_part[zz * Bc * Nc * Mc + o];
    float sp = g_sp_f[b * Nc + n];
    float st = g_st_f[b * Mc + m];
    int lab = labels[b * Mc + m];
    lab = lab < 0 ? 0 : (lab >= Cc ? Cc - 1 : lab);
    float logit = logits[(b * Nc + n) * Cc + lab];

    const float invL = 1.0f / (float)Lc;
    float cost_class = -logit;
    float cost_mask = -(2.0f * pt + (float)Lc - sp - st) * invL;
    float cost_dice = 1.0f - (2.0f * pt + 1.0f) / (sp + st + 1.0f);
    out[o] = cost_class + cost_mask + cost_dice;
}

extern "C" void kernel_launch(void* const* d_in, const int* in_sizes, int n_in,
                              void* d_out, int out_size) {
    const float* pred_logits = (const float*)d_in[0]; // (4,100,81) f32
    const float* pred_masks = (const float*)d_in[1];  // (4,100,256,256) f32
    const int* gt_labels = (const int*)d_in[2];       // (4,20) int32
    const float* gt_masks = (const float*)d_in[3];    // (4,20,256,256) f32
    float* out = (float*)d_out;                       // (4,100,20) f32

    cudaFuncSetAttribute(main_kernel, cudaFuncAttributeMaxDynamicSharedMemorySize,
                         SMEM_TOTAL);
    dim3 grid(LSEG, Bc);
    main_kernel<<<grid, TPB, SMEM_TOTAL>>>(pred_masks, gt_masks);
    reduce_kernel<<<1, 512>>>();
    combine_kernel<<<(Bc * Nc * Mc + 255) / 256, 256>>>(pred_logits, gt_labels, out);
}

// round 8
// speedup vs baseline: 3.7055x; 1.6644x over previous
#include <cuda_runtime.h>
#include <cstdint>

// Problem constants
#define Bc 4
#define Nc 100
#define Cc 81
#define Mc 20
#define Lc 65536
#define LSEG 64
#define SEGLEN (Lc / LSEG)    // 1024
#define KCH 64                // K per chunk (bf16 SW128 row = 128B)
#define NCHUNK (SEGLEN / KCH) // 16
#define TPB 256

// Partial-sum scratch
__device__ float g_pt_part[LSEG * Bc * Nc * Mc]; // 2 MB
__device__ float g_sp_part[LSEG * Bc * Nc];
__device__ float g_st_part[LSEG * Bc * Mc];
__device__ float g_sp_f[Bc * Nc];
__device__ float g_st_f[Bc * Mc];

// sigmoid(x) = 0.5*tanh(x/2) + 0.5  (1 MUFU instead of EX2+RCP)
__device__ __forceinline__ float fsigmoid(float x) {
    float t;
    asm("tanh.approx.f32 %0, %1;" : "=f"(t) : "f"(x * 0.5f));
    return fmaf(0.5f, t, 0.5f);
}
__device__ __forceinline__ uint32_t smem_u32(const void* p) {
    uint32_t a;
    asm("{ .reg .u64 t; cvta.to.shared.u64 t, %1; cvt.u32.u64 %0, t; }"
        : "=r"(a) : "l"(p));
    return a;
}
__device__ __forceinline__ uint32_t sw128(uint32_t off) {
    return off ^ ((off >> 3) & 0x70);
}
__device__ __forceinline__ void ldmx4(uint32_t addr, uint32_t& r0, uint32_t& r1,
                                      uint32_t& r2, uint32_t& r3) {
    asm volatile("ldmatrix.sync.aligned.m8n8.x4.shared.b16 {%0,%1,%2,%3}, [%4];"
                 : "=r"(r0), "=r"(r1), "=r"(r2), "=r"(r3) : "r"(addr));
}
__device__ __forceinline__ void ldmx2(uint32_t addr, uint32_t& r0, uint32_t& r1) {
    asm volatile("ldmatrix.sync.aligned.m8n8.x2.shared.b16 {%0,%1}, [%2];"
                 : "=r"(r0), "=r"(r1) : "r"(addr));
}
__device__ __forceinline__ void mma16816(float* c, const uint32_t* a, uint32_t b0,
                                         uint32_t b1) {
    asm volatile(
        "mma.sync.aligned.m16n8k16.row.col.f32.bf16.bf16.f32 "
        "{%0,%1,%2,%3}, {%4,%5,%6,%7}, {%8,%9}, {%0,%1,%2,%3};"
        : "+f"(c[0]), "+f"(c[1]), "+f"(c[2]), "+f"(c[3])
        : "r"(a[0]), "r"(a[1]), "r"(a[2]), "r"(a[3]), "r"(b0), "r"(b1));
}
__device__ __forceinline__ uint32_t packbf(float lo, float hi) {
    uint32_t r;
    asm("cvt.rn.satfinite.bf16x2.f32 %0, %1, %2;" : "=r"(r) : "f"(hi), "f"(lo));
    return r;
}

__global__ void __launch_bounds__(TPB, 2) main_kernel(const float* __restrict__ pm,
                                                      const float* __restrict__ gt) {
    __shared__ __align__(128) char pbf[2][16384]; // p bf16: 128 rows x 128B
    __shared__ __align__(128) char tbf[2][4096];  // t bf16: 32 rows x 128B

    const int tid = threadIdx.x, wid = tid >> 5, lane = tid & 31;
    const int z = blockIdx.x, b = blockIdx.y;
    const float* pmb = pm + (size_t)(b * Nc) * Lc + z * SEGLEN;
    const float* gtb = gt + (size_t)(b * Mc) * Lc + z * SEGLEN;

    // Zero t pad rows 20-31 (both buffers) — covered by the chunk-0 sync.
    {
        uint4 zz = {0, 0, 0, 0};
        for (int i = tid; i < 2 * 1536 / 16; i += TPB) {
            int bi = i < 96 ? 0 : 1;
            int off = (i - bi * 96) * 16;
            *(uint4*)(&tbf[bi][2560 + off]) = zz;
        }
    }

    // Per-lane ldmatrix address components. Swizzle decomposition:
    //   sw128(row*128 + kb) = row*128 + (kb ^ ((row&7)<<4)) for kb in [0,128)
    const int lr = lane & 7;
    const int a_row = 16 * wid + ((lane >> 3) & 1) * 8 + lr;
    const uint32_t a_base = (uint32_t)a_row * 128;
    const uint32_t a_x = (uint32_t)(a_row & 7) << 4;
    const uint32_t a_kb = ((lane >> 4) & 1) * 16;
    const int b01_row = ((lane >> 4) & 1) * 8 + lr;
    const uint32_t b01_base = (uint32_t)b01_row * 128;
    const uint32_t b01_x = (uint32_t)(b01_row & 7) << 4;
    const uint32_t b01_kb = ((lane >> 3) & 1) * 16;
    const int b2_row = 16 + lr;
    const uint32_t b2_base = (uint32_t)b2_row * 128;
    const uint32_t b2_x = (uint32_t)(b2_row & 7) << 4;
    const uint32_t b2_kb = ((lane >> 3) & 1) * 16;

    float acc[3][4];
#pragma unroll
    for (int j = 0; j < 3; j++)
#pragma unroll
        for (int q = 0; q < 4; q++) acc[j][q] = 0.f;
    float sp_loc[7] = {0, 0, 0, 0, 0, 0, 0};
    float st0 = 0.f, st1 = 0.f;

    // Per-thread load slots: p rows via j=tid+k*256 (j<1600), t rows 0-19.
    const int prow = 0; // computed per k below
    (void)prow;

    float4 pr[7], tr0, tr1;
    // Load chunk 0
#pragma unroll
    for (int k = 0; k < 7; k++) {
        int j = tid + k * TPB;
        if (j < 1600) {
            int row = j >> 4, cc = j & 15;
            pr[k] = __ldcs((const float4*)(pmb + (size_t)row * Lc) + cc);
        }
    }
    {
        int row = tid >> 4, cc = tid & 15;
        tr0 = __ldcs((const float4*)(gtb + (size_t)row * Lc) + cc);
        if (tid < 64)
            tr1 = __ldcs((const float4*)(gtb + (size_t)(16 + row) * Lc) + cc);
    }

    for (int c = 0; c < NCHUNK; c++) {
        const int buf = c & 1;
        // Convert chunk c from registers -> bf16 smem (swizzled)
#pragma unroll
        for (int k = 0; k < 7; k++) {
            int j = tid + k * TPB;
            if (j < 1600) {
                int row = j >> 4, cc = j & 15;
                float s0 = fsigmoid(pr[k].x), s1 = fsigmoid(pr[k].y);
                float s2 = fsigmoid(pr[k].z), s3 = fsigmoid(pr[k].w);
                sp_loc[k] += (s0 + s1) + (s2 + s3);
                uint2 w = {packbf(s0, s1), packbf(s2, s3)};
                *(uint2*)(&pbf[buf][sw128((uint32_t)(row * 128 + cc * 8))]) = w;
            }
        }
        {
            int row = tid >> 4, cc = tid & 15;
            st0 += (tr0.x + tr0.y) + (tr0.z + tr0.w);
            uint2 w = {packbf(tr0.x, tr0.y), packbf(tr0.z, tr0.w)};
            *(uint2*)(&tbf[buf][sw128((uint32_t)(row * 128 + cc * 8))]) = w;
            if (tid < 64) {
                st1 += (tr1.x + tr1.y) + (tr1.z + tr1.w);
                uint2 w2 = {packbf(tr1.x, tr1.y), packbf(tr1.z, tr1.w)};
                *(uint2*)(&tbf[buf][sw128((uint32_t)((16 + row) * 128 + cc * 8))]) = w2;
            }
        }
        // Issue loads for chunk c+1 (latency hidden behind sync + MMA)
        if (c + 1 < NCHUNK) {
            const int c1 = (c + 1) * KCH;
#pragma unroll
            for (int k = 0; k < 7; k++) {
                int j = tid + k * TPB;
                if (j < 1600) {
                    int row = j >> 4, cc = j & 15;
                    pr[k] = __ldcs((const float4*)(pmb + (size_t)row * Lc + c1) + cc);
                }
            }
            int row = tid >> 4, cc = tid & 15;
            tr0 = __ldcs((const float4*)(gtb + (size_t)row * Lc + c1) + cc);
            if (tid < 64)
                tr1 = __ldcs((const float4*)(gtb + (size_t)(16 + row) * Lc + c1) + cc);
        }
        __syncthreads(); // bf16[buf] ready; also fences prior MMA reads of buf

        // Warp-level GEMM on bf16[buf]: 4 k16-steps
        const uint32_t pb = smem_u32(&pbf[buf][0]);
        const uint32_t tb = smem_u32(&tbf[buf][0]);
#pragma unroll
        for (int ks = 0; ks < 4; ks++) {
            const uint32_t kb = (uint32_t)ks * 32;
            uint32_t a[4], b0[2], b1[2], b2r[2];
            ldmx4(pb + a_base + ((a_kb + kb) ^ a_x), a[0], a[1], a[2], a[3]);
            ldmx4(tb + b01_base + ((b01_kb + kb) ^ b01_x), b0[0], b0[1], b1[0], b1[1]);
            ldmx2(tb + b2_base + ((b2_kb + kb) ^ b2_x), b2r[0], b2r[1]);
            mma16816(acc[0], a, b0[0], b0[1]);
            mma16816(acc[1], a, b1[0], b1[1]);
            mma16816(acc[2], a, b2r[0], b2r[1]);
        }
    }

    // ---- Epilogue: write pt partials (rows<100, cols<20) ----
    {
        const int gr = lane >> 2, qc = lane & 3;
        const int r0 = 16 * wid + gr, r1 = r0 + 8;
#pragma unroll
        for (int j = 0; j < 3; j++) {
            int col = 8 * j + 2 * qc;
            if (col + 1 < Mc) {
                if (r0 < Nc) {
                    float2 v = {acc[j][0], acc[j][1]};
                    *(float2*)&g_pt_part[((z * Bc + b) * Nc + r0) * Mc + col] = v;
                }
                if (r1 < Nc) {
                    float2 v = {acc[j][2], acc[j][3]};
                    *(float2*)&g_pt_part[((z * Bc + b) * Nc + r1) * Mc + col] = v;
                }
            }
        }
    }
    // sp partials: 16-lane groups share a p-row
#pragma unroll
    for (int k = 0; k < 7; k++) {
        float v = sp_loc[k];
#pragma unroll
        for (int o = 8; o; o >>= 1) v += __shfl_down_sync(0xffffffffu, v, o, 16);
        int row = (tid + k * TPB) >> 4;
        if ((lane & 15) == 0 && row < Nc)
            g_sp_part[(z * Bc + b) * Nc + row] = v;
    }
    // st partials
    {
        float v = st0;
#pragma unroll
        for (int o = 8; o; o >>= 1) v += __shfl_down_sync(0xffffffffu, v, o, 16);
        if ((lane & 15) == 0) g_st_part[(z * Bc + b) * Mc + (tid >> 4)] = v;
        float u = st1;
#pragma unroll
        for (int o = 8; o; o >>= 1) u += __shfl_down_sync(0xffffffffu, u, o, 16);
        if ((lane & 15) == 0 && tid < 64)
            g_st_part[(z * Bc + b) * Mc + 16 + (tid >> 4)] = u;
    }
}

// Reduce sp/st partials over z (1 block)
__global__ void reduce_kernel() {
    int i = threadIdx.x;
    if (i < Bc * Nc) {
        float s = 0.f;
#pragma unroll 8
        for (int zz = 0; zz < LSEG; zz++) s += g_sp_part[zz * Bc * Nc + i];
        g_sp_f[i] = s;
    } else if (i < Bc * Nc + Bc * Mc) {
        int j = i - Bc * Nc;
        float s = 0.f;
#pragma unroll 8
        for (int zz = 0; zz < LSEG; zz++) s += g_st_part[zz * Bc * Mc + j];
        g_st_f[j] = s;
    }
}

// Combine: thread per output, sums LSEG pt partials.
// gt_labels is int32 (JAX x64-disabled); clamp so bad labels can't trap.
__global__ void combine_kernel(const float* __restrict__ logits,
                               const int* __restrict__ labels,
                               float* __restrict__ out) {
    int o = blockIdx.x * 256 + threadIdx.x;
    if (o >= Bc * Nc * Mc) return;
    int m = o % Mc;
    int n = (o / Mc) % Nc;
    int b = o / (Mc * Nc);
    float pt = 0.f;
#pragma unroll 8
    for (int zz = 0; zz < LSEG; zz++) pt += g_pt_part[zz * Bc * Nc * Mc + o];
    float sp = g_sp_f[b * Nc + n];
    float st = g_st_f[b * Mc + m];
    int lab = labels[b * Mc + m];
    lab = lab < 0 ? 0 : (lab >= Cc ? Cc - 1 : lab);
    float logit = logits[(b * Nc + n) * Cc + lab];

    const float invL = 1.0f / (float)Lc;
    float cost_class = -logit;
    float cost_mask = -(2.0f * pt + (float)Lc - sp - st) * invL;
    float cost_dice = 1.0f - (2.0f * pt + 1.0f) / (sp + st + 1.0f);
    out[o] = cost_class + cost_mask + cost_dice;
}

extern "C" void kernel_launch(void* const* d_in, const int* in_sizes, int n_in,
                              void* d_out, int out_size) {
    const float* pred_logits = (const float*)d_in[0]; // (4,100,81) f32
    const float* pred_masks = (const float*)d_in[1];  // (4,100,256,256) f32
    const int* gt_labels = (const int*)d_in[2];       // (4,20) int32
    const float* gt_masks = (const float*)d_in[3];    // (4,20,256,256) f32
    float* out = (float*)d_out;                       // (4,100,20) f32

    dim3 grid(LSEG, Bc);
    main_kernel<<<grid, TPB>>>(pred_masks, gt_masks);
    reduce_kernel<<<1, 512>>>();
    combine_kernel<<<(Bc * Nc * Mc + 255) / 256, 256>>>(pred_logits, gt_labels, out);
}

// round 9
// speedup vs baseline: 4.4344x; 1.1967x over previous
#include <cuda_runtime.h>
#include <cstdint>

// Problem constants
#define Bc 4
#define Nc 100
#define Cc 81
#define Mc 20
#define Lc 65536
#define LSEG 64
#define SEGLEN (Lc / LSEG)    // 1024
#define KCH 64                // K per chunk (bf16 SW128 row = 128B)
#define NCHUNK (SEGLEN / KCH) // 16
#define TPB 256

// Final accumulators (zeroed by zero_kernel each run; REDG-accumulated by main)
__device__ float g_pt[Bc * Nc * Mc];
__device__ float g_sp_f[Bc * Nc];
__device__ float g_st_f[Bc * Mc];

// sigmoid(x) = 0.5*tanh(x/2) + 0.5  (1 MUFU)
__device__ __forceinline__ float fsigmoid(float x) {
    float t;
    asm("tanh.approx.f32 %0, %1;" : "=f"(t) : "f"(x * 0.5f));
    return fmaf(0.5f, t, 0.5f);
}
__device__ __forceinline__ uint32_t smem_u32(const void* p) {
    uint32_t a;
    asm("{ .reg .u64 t; cvta.to.shared.u64 t, %1; cvt.u32.u64 %0, t; }"
        : "=r"(a) : "l"(p));
    return a;
}
__device__ __forceinline__ uint32_t sw128(uint32_t off) {
    return off ^ ((off >> 3) & 0x70);
}
__device__ __forceinline__ void ldmx4(uint32_t addr, uint32_t& r0, uint32_t& r1,
                                      uint32_t& r2, uint32_t& r3) {
    asm volatile("ldmatrix.sync.aligned.m8n8.x4.shared.b16 {%0,%1,%2,%3}, [%4];"
                 : "=r"(r0), "=r"(r1), "=r"(r2), "=r"(r3) : "r"(addr));
}
__device__ __forceinline__ void ldmx2(uint32_t addr, uint32_t& r0, uint32_t& r1) {
    asm volatile("ldmatrix.sync.aligned.m8n8.x2.shared.b16 {%0,%1}, [%2];"
                 : "=r"(r0), "=r"(r1) : "r"(addr));
}
__device__ __forceinline__ void mma16816(float* c, const uint32_t* a, uint32_t b0,
                                         uint32_t b1) {
    asm volatile(
        "mma.sync.aligned.m16n8k16.row.col.f32.bf16.bf16.f32 "
        "{%0,%1,%2,%3}, {%4,%5,%6,%7}, {%8,%9}, {%0,%1,%2,%3};"
        : "+f"(c[0]), "+f"(c[1]), "+f"(c[2]), "+f"(c[3])
        : "r"(a[0]), "r"(a[1]), "r"(a[2]), "r"(a[3]), "r"(b0), "r"(b1));
}
__device__ __forceinline__ uint32_t packbf(float lo, float hi) {
    uint32_t r;
    asm("cvt.rn.satfinite.bf16x2.f32 %0, %1, %2;" : "=r"(r) : "f"(hi), "f"(lo));
    return r;
}

// Zero final accumulators (one small block)
__global__ void zero_kernel() {
    for (int i = threadIdx.x; i < Bc * Nc * Mc; i += 256) g_pt[i] = 0.f;
    for (int i = threadIdx.x; i < Bc * Nc; i += 256) g_sp_f[i] = 0.f;
    for (int i = threadIdx.x; i < Bc * Mc; i += 256) g_st_f[i] = 0.f;
}

__global__ void __launch_bounds__(TPB, 2) main_kernel(const float* __restrict__ pm,
                                                      const float* __restrict__ gt) {
    __shared__ __align__(128) char pbf[2][16384]; // p bf16: 128 rows x 128B
    __shared__ __align__(128) char tbf[2][4096];  // t bf16: 32 rows x 128B

    const int tid = threadIdx.x, wid = tid >> 5, lane = tid & 31;
    const int z = blockIdx.x, b = blockIdx.y;
    const float* pmb = pm + (size_t)(b * Nc) * Lc + z * SEGLEN;
    const float* gtb = gt + (size_t)(b * Mc) * Lc + z * SEGLEN;

    // Zero t pad rows 20-31 (both buffers) — covered by the chunk-0 sync.
    {
        uint4 zz = {0, 0, 0, 0};
        for (int i = tid; i < 2 * 1536 / 16; i += TPB) {
            int bi = i < 96 ? 0 : 1;
            int off = (i - bi * 96) * 16;
            *(uint4*)(&tbf[bi][2560 + off]) = zz;
        }
    }

    // Per-lane ldmatrix address components. Swizzle decomposition:
    //   sw128(row*128 + kb) = row*128 + (kb ^ ((row&7)<<4)) for kb in [0,128)
    const int lr = lane & 7;
    const int a_row = 16 * wid + ((lane >> 3) & 1) * 8 + lr;
    const uint32_t a_base = (uint32_t)a_row * 128;
    const uint32_t a_x = (uint32_t)(a_row & 7) << 4;
    const uint32_t a_kb = ((lane >> 4) & 1) * 16;
    const int b01_row = ((lane >> 4) & 1) * 8 + lr;
    const uint32_t b01_base = (uint32_t)b01_row * 128;
    const uint32_t b01_x = (uint32_t)(b01_row & 7) << 4;
    const uint32_t b01_kb = ((lane >> 3) & 1) * 16;
    const int b2_row = 16 + lr;
    const uint32_t b2_base = (uint32_t)b2_row * 128;
    const uint32_t b2_x = (uint32_t)(b2_row & 7) << 4;
    const uint32_t b2_kb = ((lane >> 3) & 1) * 16;

    float acc[3][4];
#pragma unroll
    for (int j = 0; j < 3; j++)
#pragma unroll
        for (int q = 0; q < 4; q++) acc[j][q] = 0.f;
    float sp_loc[7] = {0, 0, 0, 0, 0, 0, 0};
    float st0 = 0.f, st1 = 0.f;

    float4 pr[7], tr0, tr1;
    // Load chunk 0
#pragma unroll
    for (int k = 0; k < 7; k++) {
        int j = tid + k * TPB;
        if (j < 1600) {
            int row = j >> 4, cc = j & 15;
            pr[k] = __ldcs((const float4*)(pmb + (size_t)row * Lc) + cc);
        }
    }
    {
        int row = tid >> 4, cc = tid & 15;
        tr0 = __ldcs((const float4*)(gtb + (size_t)row * Lc) + cc);
        if (tid < 64)
            tr1 = __ldcs((const float4*)(gtb + (size_t)(16 + row) * Lc) + cc);
    }

    for (int c = 0; c < NCHUNK; c++) {
        const int buf = c & 1;
        // Convert chunk c from registers -> bf16 smem (swizzled)
#pragma unroll
        for (int k = 0; k < 7; k++) {
            int j = tid + k * TPB;
            if (j < 1600) {
                int row = j >> 4, cc = j & 15;
                float s0 = fsigmoid(pr[k].x), s1 = fsigmoid(pr[k].y);
                float s2 = fsigmoid(pr[k].z), s3 = fsigmoid(pr[k].w);
                sp_loc[k] += (s0 + s1) + (s2 + s3);
                uint2 w = {packbf(s0, s1), packbf(s2, s3)};
                *(uint2*)(&pbf[buf][sw128((uint32_t)(row * 128 + cc * 8))]) = w;
            }
        }
        {
            int row = tid >> 4, cc = tid & 15;
            st0 += (tr0.x + tr0.y) + (tr0.z + tr0.w);
            uint2 w = {packbf(tr0.x, tr0.y), packbf(tr0.z, tr0.w)};
            *(uint2*)(&tbf[buf][sw128((uint32_t)(row * 128 + cc * 8))]) = w;
            if (tid < 64) {
                st1 += (tr1.x + tr1.y) + (tr1.z + tr1.w);
                uint2 w2 = {packbf(tr1.x, tr1.y), packbf(tr1.z, tr1.w)};
                *(uint2*)(&tbf[buf][sw128((uint32_t)((16 + row) * 128 + cc * 8))]) = w2;
            }
        }
        // Issue loads for chunk c+1 (latency hidden behind sync + MMA)
        if (c + 1 < NCHUNK) {
            const int c1 = (c + 1) * KCH;
#pragma unroll
            for (int k = 0; k < 7; k++) {
                int j = tid + k * TPB;
                if (j < 1600) {
                    int row = j >> 4, cc = j & 15;
                    pr[k] = __ldcs((const float4*)(pmb + (size_t)row * Lc + c1) + cc);
                }
            }
            int row = tid >> 4, cc = tid & 15;
            tr0 = __ldcs((const float4*)(gtb + (size_t)row * Lc + c1) + cc);
            if (tid < 64)
                tr1 = __ldcs((const float4*)(gtb + (size_t)(16 + row) * Lc + c1) + cc);
        }
        __syncthreads(); // bf16[buf] ready; also fences prior MMA reads of buf

        // Warp-level GEMM on bf16[buf]: 4 k16-steps
        const uint32_t pb = smem_u32(&pbf[buf][0]);
        const uint32_t tb = smem_u32(&tbf[buf][0]);
#pragma unroll
        for (int ks = 0; ks < 4; ks++) {
            const uint32_t kb = (uint32_t)ks * 32;
            uint32_t a[4], b0[2], b1[2], b2r[2];
            ldmx4(pb + a_base + ((a_kb + kb) ^ a_x), a[0], a[1], a[2], a[3]);
            ldmx4(tb + b01_base + ((b01_kb + kb) ^ b01_x), b0[0], b0[1], b1[0], b1[1]);
            ldmx2(tb + b2_base + ((b2_kb + kb) ^ b2_x), b2r[0], b2r[1]);
            mma16816(acc[0], a, b0[0], b0[1]);
            mma16816(acc[1], a, b1[0], b1[1]);
            mma16816(acc[2], a, b2r[0], b2r[1]);
        }
    }

    // ---- Epilogue: REDG-accumulate into final buffers (no partials) ----
    {
        const int gr = lane >> 2, qc = lane & 3;
        const int r0 = 16 * wid + gr, r1 = r0 + 8;
#pragma unroll
        for (int j = 0; j < 3; j++) {
            int col = 8 * j + 2 * qc;
            if (col + 1 < Mc) {
                if (r0 < Nc) {
                    atomicAdd(&g_pt[(b * Nc + r0) * Mc + col], acc[j][0]);
                    atomicAdd(&g_pt[(b * Nc + r0) * Mc + col + 1], acc[j][1]);
                }
                if (r1 < Nc) {
                    atomicAdd(&g_pt[(b * Nc + r1) * Mc + col], acc[j][2]);
                    atomicAdd(&g_pt[(b * Nc + r1) * Mc + col + 1], acc[j][3]);
                }
            }
        }
    }
    // sp: 16-lane groups share a p-row
#pragma unroll
    for (int k = 0; k < 7; k++) {
        float v = sp_loc[k];
#pragma unroll
        for (int o = 8; o; o >>= 1) v += __shfl_down_sync(0xffffffffu, v, o, 16);
        int row = (tid + k * TPB) >> 4;
        if ((lane & 15) == 0 && row < Nc) atomicAdd(&g_sp_f[b * Nc + row], v);
    }
    // st
    {
        float v = st0;
#pragma unroll
        for (int o = 8; o; o >>= 1) v += __shfl_down_sync(0xffffffffu, v, o, 16);
        if ((lane & 15) == 0) atomicAdd(&g_st_f[b * Mc + (tid >> 4)], v);
        float u = st1;
#pragma unroll
        for (int o = 8; o; o >>= 1) u += __shfl_down_sync(0xffffffffu, u, o, 16);
        if ((lane & 15) == 0 && tid < 64)
            atomicAdd(&g_st_f[b * Mc + 16 + (tid >> 4)], u);
    }
}

// Combine: thread per output; everything already reduced.
// gt_labels is int32 (JAX x64-disabled); clamp so bad labels can't trap.
__global__ void combine_kernel(const float* __restrict__ logits,
                               const int* __restrict__ labels,
                               float* __restrict__ out) {
    int o = blockIdx.x * 256 + threadIdx.x;
    if (o >= Bc * Nc * Mc) return;
    int m = o % Mc;
    int n = (o / Mc) % Nc;
    int b = o / (Mc * Nc);
    float pt = g_pt[o];
    float sp = g_sp_f[b * Nc + n];
    float st = g_st_f[b * Mc + m];
    int lab = labels[b * Mc + m];
    lab = lab < 0 ? 0 : (lab >= Cc ? Cc - 1 : lab);
    float logit = logits[(b * Nc + n) * Cc + lab];

    const float invL = 1.0f / (float)Lc;
    float cost_class = -logit;
    float cost_mask = -(2.0f * pt + (float)Lc - sp - st) * invL;
    float cost_dice = 1.0f - (2.0f * pt + 1.0f) / (sp + st + 1.0f);
    out[o] = cost_class + cost_mask + cost_dice;
}

extern "C" void kernel_launch(void* const* d_in, const int* in_sizes, int n_in,
                              void* d_out, int out_size) {
    const float* pred_logits = (const float*)d_in[0]; // (4,100,81) f32
    const float* pred_masks = (const float*)d_in[1];  // (4,100,256,256) f32
    const int* gt_labels = (const int*)d_in[2];       // (4,20) int32
    const float* gt_masks = (const float*)d_in[3];    // (4,20,256,256) f32
    float* out = (float*)d_out;                       // (4,100,20) f32

    zero_kernel<<<1, 256>>>();
    dim3 grid(LSEG, Bc);
    main_kernel<<<grid, TPB>>>(pred_masks, gt_masks);
    combine_kernel<<<(Bc * Nc * Mc + 255) / 256, 256>>>(pred_logits, gt_labels, out);
}